// round 13
// baseline (speedup 1.0000x reference)
#include <cuda_runtime.h>
#include <cstdint>

#define BB 128
#define NN 16384
#define KK 32
#define CAP 2048                       // per-row candidate cap (bench needs ~100)
#define THR 2.5f                       // fast-path threshold
#define NBINS 2048                     // fallback histogram (11-bit)
#define TPB 256
#define BPT (NBINS / TPB)              // 8 bins per thread (fallback scan)

#define ZSEG 512                       // n-positions per CTA
#define SEGS (NN / ZSEG)               // 32 CTAs per row
#define ZGRID (BB * SEGS)              // 4096
#define ZF4_PER_T (ZSEG * KK / 4 / TPB)  // 16 float4 stores per thread
#define MASKW (ZSEG / 32)              // 16 mask words

// eps = FLT_EPSILON = 2^-23 ; eps^2 = 2^-46 ; 1/eps^2 = 2^46 (exact powers of 2)
#define EPSf    1.1920929e-07f
#define E2f     1.4210854715202004e-14f
#define INV_E2f 7.0368744177664e13f

// Device scratch (allocation-free rule: __device__ globals; zero-initialized;
// g_cnt/g_done reset by the finalizing CTA each launch for graph replays).
__device__ float    g_cand[BB * CAP];
__device__ unsigned g_cidx[BB * CAP];
__device__ unsigned g_cnt[BB];
__device__ unsigned g_done[BB];

__device__ __forceinline__ unsigned key_of(float f) {
    unsigned u = __float_as_uint(f);
    return (u & 0x80000000u) ? ~u : (u | 0x80000000u);
}
__device__ __forceinline__ float key_to_float(unsigned k) {
    unsigned u = (k & 0x80000000u) ? (k & 0x7FFFFFFFu) : ~k;
    return __uint_as_float(u);
}

// ---------------------------------------------------------------------------
// Single fused kernel, fence-light design:
//   1. collect candidates (x >= THR: provable superset of the exact top-32
//      and of every eps-window contributor, since ulp(THR) > eps) + local
//      bitmask of candidate positions.
//   2. __threadfence BEFORE the bulk stores (only the few candidate stores
//      are pending -> cheap), then the per-row completion ticket.
//   3. streaming zero-fill of this CTA's 64 KB output slab, SKIPPING
//      candidate segments (scatter becomes their sole writer -> no ordering
//      needed against the store stream). Non-candidates are exactly 0
//      (s_j >= 1 always -> relu(1-s_j) == 0).
//   4. last CTA of the row: exact rank-select of top-32, c_j = 1 - x_m_sum_j
//      (terms exactly 0/1 -> order-invariant), scatter candidate segments.
//      Overlaps the other CTAs' store streams. Exact histogram fallback for
//      non-bench inputs lives here too; its collect threshold is capped at
//      key(THR) so it covers every mask-skipped position.
// ---------------------------------------------------------------------------
__global__ void __launch_bounds__(TPB) fused_kernel(const float* __restrict__ x,
                                                    float* __restrict__ out) {
    extern __shared__ unsigned char sraw[];
    float*    cand = (float*)sraw;                   // 8 KB
    unsigned* cidx = (unsigned*)(sraw + CAP * 4);    // 8 KB
    unsigned* hist = (unsigned*)(sraw + CAP * 8);    // 8 KB (fallback only)
    __shared__ unsigned csum[TPB];
    __shared__ unsigned mask[MASKW];
    __shared__ float st[KK], sc[KK];
    __shared__ float partial[8 * KK];
    __shared__ unsigned s_m;
    __shared__ int s_bin, s_last;

    const int cid  = blockIdx.x;          // b*32 + seg
    const int b    = cid >> 5;
    const int n0   = (cid & 31) * ZSEG;
    const int tid  = threadIdx.x;
    const int lane = tid & 31;

    if (tid < MASKW) mask[tid] = 0;
    // Kick off the x loads (2 floats/thread, coalesced).
    const float2 xv = ((const float2*)(x + (size_t)b * NN + n0))[tid];
    __syncthreads();                      // mask init visible

    // ---- Threshold collect: ballot-aggregated global append + local mask ----
    float vals[2] = {xv.x, xv.y};
    #pragma unroll
    for (int c = 0; c < 2; c++) {
        const bool pred = vals[c] >= THR;
        const unsigned bm = __ballot_sync(0xFFFFFFFFu, pred);
        if (bm) {
            const int leader = __ffs(bm) - 1;
            unsigned basec = 0;
            if (lane == leader) basec = atomicAdd(&g_cnt[b], (unsigned)__popc(bm));
            basec = __shfl_sync(0xFFFFFFFFu, basec, leader);
            if (pred) {
                const unsigned p = basec + (unsigned)__popc(bm & ((1u << lane) - 1u));
                if (p < CAP) {
                    const unsigned nl = 2u * tid + c;          // 0..511 in slab
                    g_cand[b * CAP + p] = vals[c];
                    g_cidx[b * CAP + p] = (unsigned)n0 + nl;
                    atomicOr(&mask[nl >> 5], 1u << (nl & 31)); // skip-zero + scatter, consistent
                }
            }
        }
    }

    // ---- Cheap fence (only candidate stores pending) + row ticket ----
    __threadfence();
    __syncthreads();
    if (tid == 0) {
        unsigned old = atomicAdd(&g_done[b], 1u);
        s_last = (old == SEGS - 1);
    }
    __syncthreads();

    // ---- Zero this CTA's 64 KB slab, skipping candidate segments ----
    // store k of thread t covers n_local = k*32 + (t>>3): test bit (t>>3) of mask[k].
    {
        const unsigned sub = (unsigned)(tid >> 3);
        const float4 z = make_float4(0.f, 0.f, 0.f, 0.f);
        float4* basep = (float4*)out + ((size_t)b * NN + n0) * (KK / 4) + tid;
        #pragma unroll
        for (int k = 0; k < ZF4_PER_T; k++)
            if (!((mask[k] >> sub) & 1u))
                __stcs(basep + k * TPB, z);
    }

    if (!s_last) return;
    __threadfence();                      // acquire side of the ticket

    if (tid == 0) {
        s_m = g_cnt[b];
        g_cnt[b]  = 0;                    // reset for next graph replay
        g_done[b] = 0;
    }
    __syncthreads();
    unsigned cnt = s_m;

    if (cnt >= KK && cnt <= CAP) {
        // Fast path: candidates are L2-hot (written this launch by this row).
        for (unsigned i = tid; i < cnt; i += TPB) {
            cand[i] = g_cand[b * CAP + i];
            cidx[i] = g_cidx[b * CAP + i];
        }
        __syncthreads();
    } else {
        // ---- Exact fallback: 11-bit histogram select over the full row ----
        const float* xrow = x + (size_t)b * NN;
        for (int i = tid; i < NBINS; i += TPB) hist[i] = 0;
        if (tid == 0) s_m = 0;
        __syncthreads();
        for (int i = tid; i < NN; i += TPB) {
            unsigned dg = key_of(xrow[i]) >> 21;
            unsigned peers = __match_any_sync(0xFFFFFFFFu, dg);
            if ((tid & 31) == __ffs(peers) - 1)
                atomicAdd(&hist[dg], (unsigned)__popc(peers));
        }
        __syncthreads();
        {
            unsigned s = 0;
            #pragma unroll
            for (int j = 0; j < BPT; j++) s += hist[tid * BPT + j];
            csum[tid] = s;
            __syncthreads();
            #pragma unroll
            for (int off = 1; off < TPB; off <<= 1) {
                unsigned t = (tid + off < TPB) ? csum[tid + off] : 0u;
                __syncthreads();
                csum[tid] += t;
                __syncthreads();
            }
        }
        {
            unsigned incl = csum[tid];
            unsigned excl = (tid < TPB - 1) ? csum[tid + 1] : 0u;
            if (incl >= KK && excl < KK) {
                unsigned cum = excl;
                #pragma unroll
                for (int j = BPT - 1; j >= 0; j--) {
                    cum += hist[tid * BPT + j];
                    if (cum >= KK) { s_bin = tid * BPT + j; break; }
                }
            }
        }
        __syncthreads();
        const float binlo   = key_to_float((unsigned)s_bin << 21);
        // Cap at key(THR): the fallback candidate set must cover every
        // mask-skipped (never-zeroed) position, i.e. everything >= THR.
        const unsigned thrk = min(key_of(binlo - 2.0f * EPSf), key_of(THR));
        for (int i = tid; i < NN; i += TPB) {
            float v = xrow[i];
            if (key_of(v) >= thrk) {
                unsigned p = atomicAdd(&s_m, 1u);
                if (p < CAP) { cand[p] = v; cidx[p] = (unsigned)i; }
            }
        }
        __syncthreads();
        cnt = min(s_m, (unsigned)CAP);
    }
    const int m = (int)cnt;

    // ---- Rank-select top-32 (descending) among m candidates ----
    for (int i0 = tid; i0 < m; i0 += TPB) {
        unsigned kv = key_of(cand[i0]);
        int rank = 0;
        for (int i = 0; i < m; i++) {
            unsigned kw = key_of(cand[i]);
            rank += (kw > kv) || (kw == kv && i < i0);
        }
        if (rank < KK) st[rank] = cand[i0];
    }
    __syncthreads();

    // ---- c_j = 1 - x_m_sum_j, parallel: thread t = (chunk t>>5, j = t&31) ----
    {
        const int j = tid & 31, ck = tid >> 5;
        const float tj = st[j];
        float acc = 0.f;
        for (int i = ck; i < m; i += 8) {
            float d = cand[i] - tj;
            acc += fmaxf(__fmaf_rn(-d, d, E2f), 0.f) * INV_E2f;
        }
        partial[tid] = acc;               // [ck][j] at ck*32 + j == tid
    }
    __syncthreads();
    if (tid < KK) {
        float acc = 0.f;
        #pragma unroll
        for (int ck = 0; ck < 8; ck++) acc += partial[ck * KK + tid];
        sc[tid] = 1.0f - acc;             // exact: terms are exactly 0 or 1
    }
    __syncthreads();

    // ---- Scatter: sole writer of every candidate's 32-wide segment ----
    for (int w = tid; w < m * 8; w += TPB) {
        const int p = w >> 3, q = w & 7, j0 = q * 4;
        const float xvv    = cand[p];
        const unsigned idx = cidx[p];
        float d;
        float4 r;
        d = xvv - st[j0 + 0]; r.x = fmaxf(__fmaf_rn(fmaxf(__fmaf_rn(-d, d, E2f), 0.f), INV_E2f, sc[j0 + 0]), 0.f);
        d = xvv - st[j0 + 1]; r.y = fmaxf(__fmaf_rn(fmaxf(__fmaf_rn(-d, d, E2f), 0.f), INV_E2f, sc[j0 + 1]), 0.f);
        d = xvv - st[j0 + 2]; r.z = fmaxf(__fmaf_rn(fmaxf(__fmaf_rn(-d, d, E2f), 0.f), INV_E2f, sc[j0 + 2]), 0.f);
        d = xvv - st[j0 + 3]; r.w = fmaxf(__fmaf_rn(fmaxf(__fmaf_rn(-d, d, E2f), 0.f), INV_E2f, sc[j0 + 3]), 0.f);
        float4* dst = (float4*)(out + ((size_t)b * NN + idx) * KK);
        dst[q] = r;
    }
}

// ---------------------------------------------------------------------------
extern "C" void kernel_launch(void* const* d_in, const int* in_sizes, int n_in,
                              void* d_out, int out_size) {
    const float* x = (const float*)d_in[0];
    float* out = (float*)d_out;
    (void)in_sizes; (void)n_in; (void)out_size;   // shapes fixed: (128,16384), k=32

    const int smem = CAP * 8 + NBINS * 4;         // 24 KB (cand | cidx | hist)
    cudaFuncSetAttribute(fused_kernel,
                         cudaFuncAttributeMaxDynamicSharedMemorySize, smem);

    fused_kernel<<<ZGRID, TPB, smem>>>(x, out);
}

// round 14
// speedup vs baseline: 1.0359x; 1.0359x over previous
#include <cuda_runtime.h>
#include <cstdint>

#define BB 128
#define NN 16384
#define KK 32
#define CAP 2048                       // per-row candidate cap (bench needs ~100)
#define THR 2.5f                       // fast-path threshold
#define NBINS 2048                     // fallback histogram (11-bit)
#define TPB_F 256
#define BPT (NBINS / TPB_F)            // 8 bins per thread (fallback scan)

// zero_collect shape (PROVEN r9: ~39.7us): 4096 CTAs (32/row), 256 thr.
#define TPB_Z 256
#define ZSEG 512
#define ZGRID (BB * (NN / ZSEG))       // 4096
#define ZF4_PER_T (ZSEG * KK / 4 / TPB_Z)  // 16

// finalize shape: 8 CTAs per row, redundant st/sc, sliced scatter.
#define FSEG 8
#define FGRID (BB * FSEG)              // 1024

// eps = FLT_EPSILON = 2^-23 ; eps^2 = 2^-46 ; 1/eps^2 = 2^46 (exact powers of 2)
#define EPSf    1.1920929e-07f
#define E2f     1.4210854715202004e-14f
#define INV_E2f 7.0368744177664e13f

// Device scratch (allocation-free rule: __device__ globals; zero-initialized;
// g_cnt/g_done reset by the last finalize CTA per row each launch).
__device__ float    g_cand[BB * CAP];
__device__ unsigned g_cidx[BB * CAP];
__device__ unsigned g_cnt[BB];
__device__ unsigned g_done[BB];

__device__ __forceinline__ unsigned key_of(float f) {
    unsigned u = __float_as_uint(f);
    return (u & 0x80000000u) ? ~u : (u | 0x80000000u);
}
__device__ __forceinline__ float key_to_float(unsigned k) {
    unsigned u = (k & 0x80000000u) ? (k & 0x7FFFFFFFu) : ~k;
    return __uint_as_float(u);
}

// ---------------------------------------------------------------------------
// zero_collect (byte-identical to the r9 kernel that measured ~39.7us):
// streaming zero-fill of the whole output (exact for all non-candidates,
// since s_j >= 1 -> relu(1-s_j) == 0) fused with the threshold collect of
// the matching 512 x's (x >= THR: provable superset of the exact top-32 and
// of every eps-window contributor, since ulp(THR) > eps).
// ---------------------------------------------------------------------------
__global__ void __launch_bounds__(TPB_Z) zero_collect_kernel(const float* __restrict__ x,
                                                             float4* __restrict__ out) {
    const int cid  = blockIdx.x;              // b*32 + seg
    const int b    = cid >> 5;
    const int n0   = (cid & 31) * ZSEG;
    const int tid  = threadIdx.x;
    const int lane = tid & 31;

    // Issue the x loads first (2 floats/thread, coalesced), hide under stores.
    const float2 xv = ((const float2*)(x + (size_t)b * NN + n0))[tid];

    // Zero the 64 KB output slab of this segment.
    const float4 z = make_float4(0.f, 0.f, 0.f, 0.f);
    float4* basep = out + ((size_t)b * NN + n0) * (KK / 4) + tid;
    #pragma unroll
    for (int k = 0; k < ZF4_PER_T; k++)
        __stcs(basep + k * TPB_Z, z);

    // Threshold collect: ballot-aggregated global atomic append.
    float vals[2] = {xv.x, xv.y};
    #pragma unroll
    for (int c = 0; c < 2; c++) {
        const bool pred = vals[c] >= THR;
        const unsigned bm = __ballot_sync(0xFFFFFFFFu, pred);
        if (bm) {
            const int leader = __ffs(bm) - 1;
            unsigned basec = 0;
            if (lane == leader) basec = atomicAdd(&g_cnt[b], (unsigned)__popc(bm));
            basec = __shfl_sync(0xFFFFFFFFu, basec, leader);
            if (pred) {
                const unsigned p = basec + (unsigned)__popc(bm & ((1u << lane) - 1u));
                if (p < CAP) {
                    g_cand[b * CAP + p] = vals[c];
                    g_cidx[b * CAP + p] = (unsigned)(n0 + 2 * tid + c);
                }
            }
        }
    }
}

// ---------------------------------------------------------------------------
// finalize_scatter v2: 1024 CTAs (8 per row) x 256 thr. Each CTA redundantly
// rank-selects the exact top-32 and computes c_j (deterministic on the fast
// path: terms exactly 0/1 -> order-invariant), then scatters its 1/8 slice of
// candidate segments. Prefetched loads kill the dependent cold-load chain;
// c_j is chunk-parallel. Last CTA per row (tiny ticket) resets g_cnt/g_done.
// Exact histogram fallback (redundant per CTA) for non-bench inputs.
// ---------------------------------------------------------------------------
__global__ void __launch_bounds__(TPB_F) finalize_scatter_kernel(const float* __restrict__ x,
                                                                 float* __restrict__ out) {
    extern __shared__ unsigned char sraw[];
    float*    cand = (float*)sraw;                   // 8 KB
    unsigned* cidx = (unsigned*)(sraw + CAP * 4);    // 8 KB
    unsigned* hist = (unsigned*)(sraw + CAP * 8);    // 8 KB (fallback only)
    __shared__ unsigned csum[TPB_F];
    __shared__ float st[KK], sc[KK];
    __shared__ float partial[8 * KK];
    __shared__ unsigned s_m;
    __shared__ int s_bin;

    const int cid = blockIdx.x;          // b*8 + seg
    const int b   = cid >> 3;
    const int seg = cid & 7;
    const int tid = threadIdx.x;

    // Parallel prefetch: count + first 256 candidates, independent loads.
    const unsigned cnt0 = g_cnt[b];
    const float    v_pf = g_cand[b * CAP + tid];
    const unsigned i_pf = g_cidx[b * CAP + tid];
    cand[tid] = v_pf;
    cidx[tid] = i_pf;

    unsigned cnt = cnt0;
    if (cnt >= KK && cnt <= CAP) {
        // Remaining candidates beyond the prefetched 256 (rare).
        for (unsigned i = tid + TPB_F; i < cnt; i += TPB_F) {
            cand[i] = g_cand[b * CAP + i];
            cidx[i] = g_cidx[b * CAP + i];
        }
        __syncthreads();
    } else {
        // ---- Exact fallback: 11-bit histogram select over the full row ----
        const float* xrow = x + (size_t)b * NN;
        for (int i = tid; i < NBINS; i += TPB_F) hist[i] = 0;
        if (tid == 0) s_m = 0;
        __syncthreads();
        for (int i = tid; i < NN; i += TPB_F) {
            unsigned dg = key_of(xrow[i]) >> 21;
            unsigned peers = __match_any_sync(0xFFFFFFFFu, dg);
            if ((tid & 31) == __ffs(peers) - 1)
                atomicAdd(&hist[dg], (unsigned)__popc(peers));
        }
        __syncthreads();
        {
            unsigned s = 0;
            #pragma unroll
            for (int j = 0; j < BPT; j++) s += hist[tid * BPT + j];
            csum[tid] = s;
            __syncthreads();
            #pragma unroll
            for (int off = 1; off < TPB_F; off <<= 1) {
                unsigned t = (tid + off < TPB_F) ? csum[tid + off] : 0u;
                __syncthreads();
                csum[tid] += t;
                __syncthreads();
            }
        }
        {
            unsigned incl = csum[tid];
            unsigned excl = (tid < TPB_F - 1) ? csum[tid + 1] : 0u;
            if (incl >= KK && excl < KK) {
                unsigned cum = excl;
                #pragma unroll
                for (int j = BPT - 1; j >= 0; j--) {
                    cum += hist[tid * BPT + j];
                    if (cum >= KK) { s_bin = tid * BPT + j; break; }
                }
            }
        }
        __syncthreads();
        const float binlo   = key_to_float((unsigned)s_bin << 21);
        const unsigned thrk = key_of(binlo - 2.0f * EPSf);
        for (int i = tid; i < NN; i += TPB_F) {
            float v = xrow[i];
            if (key_of(v) >= thrk) {
                unsigned p = atomicAdd(&s_m, 1u);
                if (p < CAP) { cand[p] = v; cidx[p] = (unsigned)i; }
            }
        }
        __syncthreads();
        cnt = min(s_m, (unsigned)CAP);
    }
    const int m = (int)cnt;

    // ---- Rank-select top-32 (descending) among m candidates ----
    for (int i0 = tid; i0 < m; i0 += TPB_F) {
        unsigned kv = key_of(cand[i0]);
        int rank = 0;
        for (int i = 0; i < m; i++) {
            unsigned kw = key_of(cand[i]);
            rank += (kw > kv) || (kw == kv && i < i0);
        }
        if (rank < KK) st[rank] = cand[i0];
    }
    __syncthreads();

    // ---- c_j = 1 - x_m_sum_j, chunk-parallel: thread = (chunk tid>>5, j tid&31) ----
    {
        const int j = tid & 31, ck = tid >> 5;
        const float tj = st[j];
        float acc = 0.f;
        for (int i = ck; i < m; i += 8) {
            float d = cand[i] - tj;
            acc += fmaxf(__fmaf_rn(-d, d, E2f), 0.f) * INV_E2f;
        }
        partial[tid] = acc;
    }
    __syncthreads();
    if (tid < KK) {
        float acc = 0.f;
        #pragma unroll
        for (int ck = 0; ck < 8; ck++) acc += partial[ck * KK + tid];
        sc[tid] = 1.0f - acc;             // exact on fast path: terms are 0 or 1
    }
    __syncthreads();

    // ---- Scatter this CTA's slice: candidates p with (p & 7) == seg ----
    for (int w = tid; w < m * 8; w += TPB_F) {
        const int p = w >> 3;
        if ((p & 7) != seg) continue;
        const int q = w & 7, j0 = q * 4;
        const float xvv    = cand[p];
        const unsigned idx = cidx[p];
        float d;
        float4 r;
        d = xvv - st[j0 + 0]; r.x = fmaxf(__fmaf_rn(fmaxf(__fmaf_rn(-d, d, E2f), 0.f), INV_E2f, sc[j0 + 0]), 0.f);
        d = xvv - st[j0 + 1]; r.y = fmaxf(__fmaf_rn(fmaxf(__fmaf_rn(-d, d, E2f), 0.f), INV_E2f, sc[j0 + 1]), 0.f);
        d = xvv - st[j0 + 2]; r.z = fmaxf(__fmaf_rn(fmaxf(__fmaf_rn(-d, d, E2f), 0.f), INV_E2f, sc[j0 + 2]), 0.f);
        d = xvv - st[j0 + 3]; r.w = fmaxf(__fmaf_rn(fmaxf(__fmaf_rn(-d, d, E2f), 0.f), INV_E2f, sc[j0 + 3]), 0.f);
        float4* dst = (float4*)(out + ((size_t)b * NN + idx) * KK);
        dst[q] = r;
    }

    // ---- Tiny ticket among the 8 CTAs of this row: last one resets scratch.
    // (All 8 CTAs read g_cnt at kernel start; the reset happens only after
    // all 8 have ticketed, so no read/reset race.)
    __syncthreads();
    if (tid == 0) {
        __threadfence();
        unsigned old = atomicAdd(&g_done[b], 1u);
        if (old == FSEG - 1) {
            g_cnt[b]  = 0;                // ready for next graph replay
            g_done[b] = 0;
        }
    }
}

// ---------------------------------------------------------------------------
extern "C" void kernel_launch(void* const* d_in, const int* in_sizes, int n_in,
                              void* d_out, int out_size) {
    const float* x = (const float*)d_in[0];
    float* out = (float*)d_out;
    (void)in_sizes; (void)n_in; (void)out_size;   // shapes fixed: (128,16384), k=32

    const int smem_f = CAP * 8 + NBINS * 4;       // 24 KB (cand | cidx | hist)
    cudaFuncSetAttribute(finalize_scatter_kernel,
                         cudaFuncAttributeMaxDynamicSharedMemorySize, smem_f);

    zero_collect_kernel<<<ZGRID, TPB_Z>>>(x, (float4*)out);
    finalize_scatter_kernel<<<FGRID, TPB_F, smem_f>>>(x, out);
}

// round 15
// speedup vs baseline: 1.2070x; 1.1652x over previous
#include <cuda_runtime.h>
#include <cstdint>

#define BB 128
#define NN 16384
#define KK 32
#define CAP 2048                       // per-row candidate cap (bench needs ~100)
#define THR 2.5f                       // fast-path threshold
#define NBINS 2048                     // fallback histogram (11-bit)
#define TPB_F 256
#define BPT (NBINS / TPB_F)            // 8 bins per thread (fallback scan)

// zero_collect shape (PROVEN ~39.7us): 4096 CTAs (32/row), 256 thr.
#define TPB_Z 256
#define ZSEG 512
#define ZGRID (BB * (NN / ZSEG))       // 4096
#define ZF4_PER_T (ZSEG * KK / 4 / TPB_Z)  // 16

// eps = FLT_EPSILON = 2^-23 ; eps^2 = 2^-46 ; 1/eps^2 = 2^46 (exact powers of 2)
#define EPSf    1.1920929e-07f
#define E2f     1.4210854715202004e-14f
#define INV_E2f 7.0368744177664e13f

// Device scratch (allocation-free rule: __device__ globals; zero-initialized).
// (val, idx-bits) interleaved -> one 64-bit load per candidate in finalize.
__device__ float2   g_cpair[BB * CAP];
__device__ unsigned g_cnt[BB];         // reset by finalize (sole reader) per launch

__device__ __forceinline__ unsigned key_of(float f) {
    unsigned u = __float_as_uint(f);
    return (u & 0x80000000u) ? ~u : (u | 0x80000000u);
}
__device__ __forceinline__ float key_to_float(unsigned k) {
    unsigned u = (k & 0x80000000u) ? (k & 0x7FFFFFFFu) : ~k;
    return __uint_as_float(u);
}

// ---------------------------------------------------------------------------
// zero_collect (structure identical to the ~39.7us r9 kernel): streaming
// zero-fill of the whole output (exact for all non-candidates, since
// s_j >= 1 -> relu(1-s_j) == 0) fused with the threshold collect of the
// matching 512 x's (x >= THR: provable superset of the exact top-32 and of
// every eps-window contributor, since ulp(THR) > eps).
// ---------------------------------------------------------------------------
__global__ void __launch_bounds__(TPB_Z) zero_collect_kernel(const float* __restrict__ x,
                                                             float4* __restrict__ out) {
    const int cid  = blockIdx.x;              // b*32 + seg
    const int b    = cid >> 5;
    const int n0   = (cid & 31) * ZSEG;
    const int tid  = threadIdx.x;
    const int lane = tid & 31;

    // Issue the x loads first (2 floats/thread, coalesced), hide under stores.
    const float2 xv = ((const float2*)(x + (size_t)b * NN + n0))[tid];

    // Zero the 64 KB output slab of this segment.
    const float4 z = make_float4(0.f, 0.f, 0.f, 0.f);
    float4* basep = out + ((size_t)b * NN + n0) * (KK / 4) + tid;
    #pragma unroll
    for (int k = 0; k < ZF4_PER_T; k++)
        __stcs(basep + k * TPB_Z, z);

    // Threshold collect: ballot-aggregated global atomic append.
    float vals[2] = {xv.x, xv.y};
    #pragma unroll
    for (int c = 0; c < 2; c++) {
        const bool pred = vals[c] >= THR;
        const unsigned bm = __ballot_sync(0xFFFFFFFFu, pred);
        if (bm) {
            const int leader = __ffs(bm) - 1;
            unsigned basec = 0;
            if (lane == leader) basec = atomicAdd(&g_cnt[b], (unsigned)__popc(bm));
            basec = __shfl_sync(0xFFFFFFFFu, basec, leader);
            if (pred) {
                const unsigned p = basec + (unsigned)__popc(bm & ((1u << lane) - 1u));
                if (p < CAP) {
                    const unsigned idx = (unsigned)(n0 + 2 * tid + c);
                    g_cpair[b * CAP + p] = make_float2(vals[c], __uint_as_float(idx));
                }
            }
        }
    }
}

// ---------------------------------------------------------------------------
// finalize v3: 128 CTAs (ONE per row — no redundant work) x 256 thr.
//  - unconditional float2 prefetch of the first 256 candidates, issued
//    independently of (and overlapped with) the g_cnt load: one cold DRAM
//    round trip instead of a serial chain.
//  - exact rank-select of the top-32 (descending).
//  - c_j = 1 - x_m_sum_j chunk-parallel (terms exactly 0/1 on the fast path
//    -> order-invariant -> deterministic).
//  - scatter of each candidate's 32-wide output segment.
//  - per-CTA g_cnt reset (sole reader; __syncthreads orders reads first).
//  - exact histogram fallback over the full row for non-bench inputs.
// ---------------------------------------------------------------------------
__global__ void __launch_bounds__(TPB_F) finalize_kernel(const float* __restrict__ x,
                                                         float* __restrict__ out) {
    extern __shared__ unsigned char sraw[];
    float*    cand = (float*)sraw;                   // 8 KB
    unsigned* cidx = (unsigned*)(sraw + CAP * 4);    // 8 KB
    unsigned* hist = (unsigned*)(sraw + CAP * 8);    // 8 KB (fallback only)
    __shared__ unsigned csum[TPB_F];
    __shared__ float st[KK], sc[KK];
    __shared__ float partial[8 * KK];
    __shared__ unsigned s_m;
    __shared__ int s_bin;

    const int b   = blockIdx.x;
    const int tid = threadIdx.x;

    // Overlapped cold loads: prefetch candidate pair + count (independent).
    const float2  pf   = g_cpair[b * CAP + tid];     // always in-bounds (CAP=2048>=TPB_F)
    const unsigned cnt0 = g_cnt[b];
    cand[tid] = pf.x;
    cidx[tid] = __float_as_uint(pf.y);
    __syncthreads();                  // all reads of g_cnt/g_cpair complete
    if (tid == 0) g_cnt[b] = 0;       // reset for next graph replay (sole reader)

    unsigned cnt = cnt0;
    if (cnt >= KK && cnt <= CAP) {
        // Remaining candidates beyond the prefetched 256 (rare on bench).
        for (unsigned i = tid + TPB_F; i < cnt; i += TPB_F) {
            const float2 p2 = g_cpair[b * CAP + i];
            cand[i] = p2.x;
            cidx[i] = __float_as_uint(p2.y);
        }
        __syncthreads();
    } else {
        // ---- Exact fallback: 11-bit histogram select over the full row ----
        const float* xrow = x + (size_t)b * NN;
        for (int i = tid; i < NBINS; i += TPB_F) hist[i] = 0;
        if (tid == 0) s_m = 0;
        __syncthreads();
        for (int i = tid; i < NN; i += TPB_F) {
            unsigned dg = key_of(xrow[i]) >> 21;
            unsigned peers = __match_any_sync(0xFFFFFFFFu, dg);
            if ((tid & 31) == __ffs(peers) - 1)
                atomicAdd(&hist[dg], (unsigned)__popc(peers));
        }
        __syncthreads();
        {
            unsigned s = 0;
            #pragma unroll
            for (int j = 0; j < BPT; j++) s += hist[tid * BPT + j];
            csum[tid] = s;
            __syncthreads();
            #pragma unroll
            for (int off = 1; off < TPB_F; off <<= 1) {
                unsigned t = (tid + off < TPB_F) ? csum[tid + off] : 0u;
                __syncthreads();
                csum[tid] += t;
                __syncthreads();
            }
        }
        {
            unsigned incl = csum[tid];
            unsigned excl = (tid < TPB_F - 1) ? csum[tid + 1] : 0u;
            if (incl >= KK && excl < KK) {
                unsigned cum = excl;
                #pragma unroll
                for (int j = BPT - 1; j >= 0; j--) {
                    cum += hist[tid * BPT + j];
                    if (cum >= KK) { s_bin = tid * BPT + j; break; }
                }
            }
        }
        __syncthreads();
        const float binlo   = key_to_float((unsigned)s_bin << 21);
        const unsigned thrk = key_of(binlo - 2.0f * EPSf);
        for (int i = tid; i < NN; i += TPB_F) {
            float v = xrow[i];
            if (key_of(v) >= thrk) {
                unsigned p = atomicAdd(&s_m, 1u);
                if (p < CAP) { cand[p] = v; cidx[p] = (unsigned)i; }
            }
        }
        __syncthreads();
        cnt = min(s_m, (unsigned)CAP);
    }
    const int m = (int)cnt;

    // ---- Rank-select top-32 (descending) among m candidates ----
    for (int i0 = tid; i0 < m; i0 += TPB_F) {
        unsigned kv = key_of(cand[i0]);
        int rank = 0;
        for (int i = 0; i < m; i++) {
            unsigned kw = key_of(cand[i]);
            rank += (kw > kv) || (kw == kv && i < i0);
        }
        if (rank < KK) st[rank] = cand[i0];
    }
    __syncthreads();

    // ---- c_j = 1 - x_m_sum_j, chunk-parallel: thread = (chunk tid>>5, j tid&31) ----
    {
        const int j = tid & 31, ck = tid >> 5;
        const float tj = st[j];
        float acc = 0.f;
        for (int i = ck; i < m; i += 8) {
            float d = cand[i] - tj;
            acc += fmaxf(__fmaf_rn(-d, d, E2f), 0.f) * INV_E2f;
        }
        partial[tid] = acc;
    }
    __syncthreads();
    if (tid < KK) {
        float acc = 0.f;
        #pragma unroll
        for (int ck = 0; ck < 8; ck++) acc += partial[ck * KK + tid];
        sc[tid] = 1.0f - acc;             // exact on fast path: terms are 0 or 1
    }
    __syncthreads();

    // ---- Scatter: rewrite the 32-wide segment of each candidate position ----
    for (int w = tid; w < m * 8; w += TPB_F) {
        const int p = w >> 3, q = w & 7, j0 = q * 4;
        const float xvv    = cand[p];
        const unsigned idx = cidx[p];
        float d;
        float4 r;
        d = xvv - st[j0 + 0]; r.x = fmaxf(__fmaf_rn(fmaxf(__fmaf_rn(-d, d, E2f), 0.f), INV_E2f, sc[j0 + 0]), 0.f);
        d = xvv - st[j0 + 1]; r.y = fmaxf(__fmaf_rn(fmaxf(__fmaf_rn(-d, d, E2f), 0.f), INV_E2f, sc[j0 + 1]), 0.f);
        d = xvv - st[j0 + 2]; r.z = fmaxf(__fmaf_rn(fmaxf(__fmaf_rn(-d, d, E2f), 0.f), INV_E2f, sc[j0 + 2]), 0.f);
        d = xvv - st[j0 + 3]; r.w = fmaxf(__fmaf_rn(fmaxf(__fmaf_rn(-d, d, E2f), 0.f), INV_E2f, sc[j0 + 3]), 0.f);
        float4* dst = (float4*)(out + ((size_t)b * NN + idx) * KK);
        dst[q] = r;
    }
}

// ---------------------------------------------------------------------------
extern "C" void kernel_launch(void* const* d_in, const int* in_sizes, int n_in,
                              void* d_out, int out_size) {
    const float* x = (const float*)d_in[0];
    float* out = (float*)d_out;
    (void)in_sizes; (void)n_in; (void)out_size;   // shapes fixed: (128,16384), k=32

    const int smem_f = CAP * 8 + NBINS * 4;       // 24 KB (cand | cidx | hist)
    cudaFuncSetAttribute(finalize_kernel,
                         cudaFuncAttributeMaxDynamicSharedMemorySize, smem_f);

    zero_collect_kernel<<<ZGRID, TPB_Z>>>(x, (float4*)out);
    finalize_kernel<<<BB, TPB_F, smem_f>>>(x, out);
}